// round 15
// baseline (speedup 1.0000x reference)
#include <cuda_runtime.h>
#include <math.h>
#include <stdint.h>

// ---------------------------------------------------------------------------
// MLPEncoder — round 13: tf32 mma.sync edge GEMMs (tcgen05 unavailable:
// ptxas targets sm_103 without the 'a' feature). Changes vs round 11:
//  * B weights pre-arranged in mma-fragment order -> inner loop = 4x LDS.128
//  * node GEMM pairs merged into wide-N launches (2x CTAs)
//  * BN partial sums fused into edge-GEMM-3 epilogue (drops a 324MB pass)
// ---------------------------------------------------------------------------

#define B_SZ    32
#define N_NODE  100
#define N_EDGE  9900
#define HID     256
#define K_IN    200
#define ROWS_NODE (B_SZ * N_NODE)          // 3200
#define ROWS_EDGE (B_SZ * N_EDGE)          // 316800

// scratch layout (float offsets)
#define OFF_H1A  0ull
#define OFF_H1   819200ull
#define OFF_SR   1638400ull                // merged S|R  [3200,512]
#define OFF_INC  3276800ull
#define OFF_H3A  4096000ull
#define OFF_H3   4915200ull
#define OFF_AC   5734400ull                // merged A3|C3 [3200,512]
#define OFF_X2   7372800ull
#define OFF_SKIP 88473600ull
#define OFF_X4   169574400ull
#define OFF_PSUM 250675200ull
#define OFF_PSQ  250675456ull
#define OFF_WP   251182080ull
#define OFF_BP   251182592ull
#define OFF_WB   251182720ull              // 3 x 65536 u32 fragment-ordered tf32
#define SCRATCH_FLOATS 251379328ull

__device__ __align__(256) float g_scratch[SCRATCH_FLOATS];

__device__ __forceinline__ float elu1(float x) {
    return x > 0.f ? x : expm1f(x);
}

// ---------------- tf32 / mma helpers ----------------
__device__ __forceinline__ uint32_t f2tf(float x) {
    uint32_t r;
    asm("cvt.rna.tf32.f32 %0, %1;" : "=r"(r) : "f"(x));
    return r;
}

__device__ __forceinline__ void mma8(float* d, const uint32_t* a, const uint32_t* b) {
    asm volatile(
        "mma.sync.aligned.m16n8k8.row.col.f32.tf32.tf32.f32 "
        "{%0,%1,%2,%3}, {%4,%5,%6,%7}, {%8,%9}, {%0,%1,%2,%3};"
        : "+f"(d[0]), "+f"(d[1]), "+f"(d[2]), "+f"(d[3])
        : "r"(a[0]), "r"(a[1]), "r"(a[2]), "r"(a[3]), "r"(b[0]), "r"(b[1]));
}

__device__ __forceinline__ uint32_t smem_u32(const void* p) {
    uint32_t a;
    asm("{ .reg .u64 t; cvta.to.shared.u64 t, %1; cvt.u32.u64 %0, t; }"
        : "=r"(a) : "l"(p));
    return a;
}

__device__ __forceinline__ void cp16(uint32_t saddr, const void* g) {
    asm volatile("cp.async.ca.shared.global [%0], [%1], 16;"
                 :: "r"(saddr), "l"(g) : "memory");
}

// ---------------------------------------------------------------------------
// tf32 MMA GEMM over edge rows: C[316800,256] = epi(A'[.,256] @ W[256,256])
//  MODE 0: A' = Ap rows (plain, stride 256);         epi: raw
//  MODE 1: A' = elu(Ap[sJ] + Qp[sI] + preb);         epi: elu(.+bias2)
//  MODE 2: A' = elu(Ap[sJ] + Qp[sI] + extra + preb); epi: elu(.+bias2) + BN partials
// Wimg: fragment-ordered tf32 weight image (65536 u32 = 8 chunks x 8192)
// ---------------------------------------------------------------------------
#define AS_STRIDE 144
#define AS_SZ (32 * AS_STRIDE)            // 4608 u32
#define BS_SZ 8192                        // u32, fragment-ordered chunk
#define BUF_SZ (AS_SZ + BS_SZ)            // 12800 u32
#define EDGE_SMEM_BYTES (2 * BUF_SZ * 4)  // 102400 B

template <int MODE>
__global__ void __launch_bounds__(256, 1)
edge_tf32_kernel(const float* __restrict__ Ap, const float* __restrict__ Qp,
                 const float* __restrict__ extra, const float* __restrict__ preb,
                 const uint32_t* __restrict__ Wimg, const float* __restrict__ bias2,
                 float* __restrict__ C, int ldP,
                 float* __restrict__ psum, float* __restrict__ psq)
{
    extern __shared__ uint32_t dsm[];
    __shared__ int   sJ[128], sI[128];
    __shared__ float sPreb[256];

    const int tid  = threadIdx.x;
    const int row0 = blockIdx.x * 128;
    const int warp = tid >> 5, lane = tid & 31;
    const int wm = warp >> 2, wn = warp & 3;
    const int g  = lane >> 2, tg = lane & 3;

    if (MODE >= 1) {
        if (tid < 128) {
            int r  = row0 + tid;
            int b  = r / N_EDGE;
            int e  = r - b * N_EDGE;
            int i  = e / 99;
            int jr = e - i * 99;
            int j  = jr + (jr >= i);
            sJ[tid] = (b * N_NODE + j) * ldP;
            sI[tid] = (b * N_NODE + i) * ldP;
        }
        sPreb[tid] = preb[tid];
        __syncthreads();
    }

    const int arow  = tid >> 1;
    const int kh    = (tid & 1) * 16;
    const int aslot = (arow & 0x70) + ((arow & 7) << 1) + ((arow >> 3) & 1);

    const float* pJ = nullptr;
    const float* pI = nullptr;
    const float* pE = nullptr;
    const float* pA = nullptr;
    if (MODE >= 1) {
        pJ = Ap + sJ[arow];
        pI = Qp + sI[arow];
        if (MODE == 2) pE = extra + (size_t)(row0 + arow) * HID;
    } else {
        pA = Ap + (size_t)(row0 + arow) * HID;
    }

    const uint32_t smem0 = smem_u32(dsm);
    float va[16];

    auto loadA = [&](int t) {
        const int gk = t * 32 + kh;
        if (MODE == 0) {
            const float4* ap = (const float4*)(pA + gk);
#pragma unroll
            for (int q = 0; q < 4; q++) {
                float4 v = ap[q];
                va[4 * q + 0] = v.x; va[4 * q + 1] = v.y;
                va[4 * q + 2] = v.z; va[4 * q + 3] = v.w;
            }
        } else {
            const float4* jp = (const float4*)(pJ + gk);
            const float4* ip = (const float4*)(pI + gk);
#pragma unroll
            for (int q = 0; q < 4; q++) {
                float4 a = jp[q], b = ip[q];
                float4 s;
                s.x = a.x + b.x; s.y = a.y + b.y;
                s.z = a.z + b.z; s.w = a.w + b.w;
                if (MODE == 2) {
                    float4 e = ((const float4*)(pE + gk))[q];
                    s.x += e.x; s.y += e.y; s.z += e.z; s.w += e.w;
                }
                va[4 * q + 0] = s.x; va[4 * q + 1] = s.y;
                va[4 * q + 2] = s.z; va[4 * q + 3] = s.w;
            }
#pragma unroll
            for (int x = 0; x < 16; x++)
                va[x] = elu1(va[x] + sPreb[gk + x]);
        }
    };

    auto storeA = [&](int buf) {
        uint32_t* dst = dsm + buf * BUF_SZ;
#pragma unroll
        for (int x = 0; x < 16; x++)
            dst[(kh + x) * AS_STRIDE + aslot] = f2tf(va[x]);
    };

    auto loadB = [&](int t, int buf) {
        const uint32_t sb = smem0 + (uint32_t)(buf * BUF_SZ + AS_SZ) * 4;
        const uint8_t* src = (const uint8_t*)(Wimg + t * BS_SZ);
#pragma unroll
        for (int u = 0; u < 8; u++) {
            int idx = tid + u * 256;                    // 0..2047 (16B units)
            cp16(sb + (uint32_t)idx * 16, src + (size_t)idx * 16);
        }
        asm volatile("cp.async.commit_group;" ::: "memory");
    };

    // preload chunk 0
    loadA(0);
    loadB(0, 0);
    storeA(0);
    asm volatile("cp.async.wait_group 0;" ::: "memory");
    __syncthreads();

    float acc[4][8][4];
#pragma unroll
    for (int mt = 0; mt < 4; mt++)
#pragma unroll
        for (int nt = 0; nt < 8; nt++)
#pragma unroll
            for (int q = 0; q < 4; q++) acc[mt][nt][q] = 0.f;

    for (int t = 0; t < 8; t++) {
        const int cur = t & 1, nxt = cur ^ 1;
        if (t < 7) {
            loadB(t + 1, nxt);
            loadA(t + 1);
        }
        const uint32_t* As = dsm + cur * BUF_SZ;
        const uint32_t* Bs = dsm + cur * BUF_SZ + AS_SZ;
#pragma unroll
        for (int ks = 0; ks < 4; ks++) {
            const int kr0 = ks * 8 + tg;
            uint32_t af[4][4];
#pragma unroll
            for (int mt = 0; mt < 4; mt++) {
                const int mb = wm * 64 + mt * 16 + 2 * g;
                uint2 lo = *(const uint2*)&As[kr0 * AS_STRIDE + mb];
                uint2 hi = *(const uint2*)&As[(kr0 + 4) * AS_STRIDE + mb];
                af[mt][0] = lo.x; af[mt][1] = lo.y;
                af[mt][2] = hi.x; af[mt][3] = hi.y;
            }
            // fragment-ordered B: 4 conflict-free LDS.128
            uint32_t bf[8][2];
            const uint32_t* bb = Bs + (wn * 4 + ks) * 512 + lane * 4;
#pragma unroll
            for (int c4 = 0; c4 < 4; c4++) {
                uint4 v = *(const uint4*)(bb + c4 * 128);
                bf[2 * c4 + 0][0] = v.x; bf[2 * c4 + 0][1] = v.y;
                bf[2 * c4 + 1][0] = v.z; bf[2 * c4 + 1][1] = v.w;
            }
#pragma unroll
            for (int mt = 0; mt < 4; mt++)
#pragma unroll
                for (int nt = 0; nt < 8; nt++)
                    mma8(acc[mt][nt], af[mt], bf[nt]);
        }
        if (t < 7) {
            storeA(nxt);
            asm volatile("cp.async.wait_group 0;" ::: "memory");
            __syncthreads();
        }
    }

    // ---- epilogue ----
    float bcol0[8], bcol1[8];
    if (MODE >= 1) {
#pragma unroll
        for (int nt = 0; nt < 8; nt++) {
            const int col = wn * 64 + nt * 8 + tg * 2;
            bcol0[nt] = bias2[col];
            bcol1[nt] = bias2[col + 1];
        }
    }
    float ls0[8], ls1[8], lq0[8], lq1[8];
    if (MODE == 2) {
#pragma unroll
        for (int nt = 0; nt < 8; nt++) {
            ls0[nt] = 0.f; ls1[nt] = 0.f; lq0[nt] = 0.f; lq1[nt] = 0.f;
        }
    }
#pragma unroll
    for (int mt = 0; mt < 4; mt++) {
        const int ra = row0 + wm * 64 + mt * 16 + g;
#pragma unroll
        for (int nt = 0; nt < 8; nt++) {
            const int col = wn * 64 + nt * 8 + tg * 2;
            float2 o0, o1;
            if (MODE == 0) {
                o0.x = acc[mt][nt][0]; o0.y = acc[mt][nt][1];
                o1.x = acc[mt][nt][2]; o1.y = acc[mt][nt][3];
            } else {
                o0.x = elu1(acc[mt][nt][0] + bcol0[nt]);
                o0.y = elu1(acc[mt][nt][1] + bcol1[nt]);
                o1.x = elu1(acc[mt][nt][2] + bcol0[nt]);
                o1.y = elu1(acc[mt][nt][3] + bcol1[nt]);
            }
            if (MODE == 2) {
                ls0[nt] += o0.x + o1.x;
                ls1[nt] += o0.y + o1.y;
                lq0[nt] += o0.x * o0.x + o1.x * o1.x;
                lq1[nt] += o0.y * o0.y + o1.y * o1.y;
            }
            *(float2*)(C + (size_t)ra * HID + col)       = o0;
            *(float2*)(C + (size_t)(ra + 8) * HID + col) = o1;
        }
    }

    if (MODE == 2) {
        // reduce over g (lanes sharing tg own the same columns)
#pragma unroll
        for (int nt = 0; nt < 8; nt++) {
#pragma unroll
            for (int off = 4; off <= 16; off <<= 1) {
                ls0[nt] += __shfl_xor_sync(0xffffffffu, ls0[nt], off);
                ls1[nt] += __shfl_xor_sync(0xffffffffu, ls1[nt], off);
                lq0[nt] += __shfl_xor_sync(0xffffffffu, lq0[nt], off);
                lq1[nt] += __shfl_xor_sync(0xffffffffu, lq1[nt], off);
            }
        }
        if (g == 0) {
#pragma unroll
            for (int nt = 0; nt < 8; nt++) {
                const int col = wn * 64 + nt * 8 + tg * 2;
                atomicAdd(psum + col,     ls0[nt]);
                atomicAdd(psum + col + 1, ls1[nt]);
                atomicAdd(psq  + col,     lq0[nt]);
                atomicAdd(psq  + col + 1, lq1[nt]);
            }
        }
    }
}

// ---------------------------------------------------------------------------
// Weight prep: tf32-round W (row-major [k][n], 256x256) and write in mma
// fragment order: u32 idx = chunk*8192 + ((wn*4+ks)*4 + c4)*128 + lane*4 + w
//   k: chunk=k>>5, kk=k&31, ks=kk>>3, r=kk&7, tg=r&3, h=r>>2
//   n: wn=n>>6, rem=n&63, nt=rem>>3, g=rem&7;  lane=g*4+tg; c4=nt>>1; w=(nt&1)*2+h
// ---------------------------------------------------------------------------
__global__ void __launch_bounds__(256)
wprep_kernel(const float* __restrict__ W2, const float* __restrict__ W4,
             const float* __restrict__ Ws, uint32_t* __restrict__ out)
{
    int i = blockIdx.x * 256 + threadIdx.x;   // 0..196607
    int m   = i >> 16;
    int idx = i & 65535;
    const float* src = (m == 0) ? W2 : (m == 1) ? W4 : Ws;
    int k = idx >> 8, n = idx & 255;
    int chunk = k >> 5, kk = k & 31;
    int ks = kk >> 3, r = kk & 7, tg = r & 3, h = r >> 2;
    int wn = n >> 6, rem = n & 63, nt = rem >> 3, gg = rem & 7;
    int lane = gg * 4 + tg;
    int c4 = nt >> 1, w = (nt & 1) * 2 + h;
    int pos = chunk * 8192 + ((wn * 4 + ks) * 4 + c4) * 128 + lane * 4 + w;
    out[m * 65536 + pos] = f2tf(src[idx]);
}

// ---------------------------------------------------------------------------
// Generic fp32 tiled GEMM (node-level, exact). Bm_hi: optional second weight
// block for merged wide-N calls (col0 >= 256 reads Bm_hi at col0-256).
// ---------------------------------------------------------------------------
template <int BK, bool DO_ELU, bool HAS_BIAS>
__global__ void __launch_bounds__(256, 2)
gemm_kernel(const float* __restrict__ A, const float* __restrict__ Bm,
            const float* __restrict__ Bm_hi,
            const float* __restrict__ bias, float* __restrict__ C,
            int K, int ldb, int ldc)
{
    const int tid  = threadIdx.x;
    const int tx   = tid & 15;
    const int ty   = tid >> 4;
    const int row0 = blockIdx.x * 128;
    const int col0 = blockIdx.y * 128;
    int colB = col0;
    const float* B = Bm;
    if (Bm_hi != nullptr && col0 >= 256) { B = Bm_hi; colB = col0 - 256; }

    __shared__ float As[BK][132];
    __shared__ float Bs[BK][128];

    float acc[8][8];
#pragma unroll
    for (int i = 0; i < 8; i++)
#pragma unroll
        for (int j = 0; j < 8; j++) acc[i][j] = 0.f;

    const int NT = K / BK;
    for (int t = 0; t < NT; t++) {
        const int k0 = t * BK;
        if constexpr (BK == 8) {
            const int am = tid >> 1, ac = (tid & 1) * 4;
            float4 v = *(const float4*)(A + (size_t)(row0 + am) * K + k0 + ac);
            As[ac + 0][am] = v.x; As[ac + 1][am] = v.y;
            As[ac + 2][am] = v.z; As[ac + 3][am] = v.w;
            const int bk = tid >> 5, bn = (tid & 31) * 4;
            *(float4*)&Bs[bk][bn] =
                *(const float4*)(B + (size_t)(k0 + bk) * ldb + colB + bn);
        } else {
            const int am = tid >> 1, ac = (tid & 1) * 8;
            const float* ap = A + (size_t)(row0 + am) * K + k0 + ac;
            float4 v0 = *(const float4*)(ap);
            float4 v1 = *(const float4*)(ap + 4);
            As[ac + 0][am] = v0.x; As[ac + 1][am] = v0.y;
            As[ac + 2][am] = v0.z; As[ac + 3][am] = v0.w;
            As[ac + 4][am] = v1.x; As[ac + 5][am] = v1.y;
            As[ac + 6][am] = v1.z; As[ac + 7][am] = v1.w;
            const int bk = tid >> 4, bn = (tid & 15) * 8;
            const float* bp = B + (size_t)(k0 + bk) * ldb + colB + bn;
            *(float4*)&Bs[bk][bn]     = *(const float4*)(bp);
            *(float4*)&Bs[bk][bn + 4] = *(const float4*)(bp + 4);
        }
        __syncthreads();
#pragma unroll
        for (int k = 0; k < BK; k++) {
            float a[8], bb[8];
            *(float4*)&a[0]  = *(const float4*)&As[k][ty * 8];
            *(float4*)&a[4]  = *(const float4*)&As[k][ty * 8 + 4];
            *(float4*)&bb[0] = *(const float4*)&Bs[k][tx * 8];
            *(float4*)&bb[4] = *(const float4*)&Bs[k][tx * 8 + 4];
#pragma unroll
            for (int i = 0; i < 8; i++)
#pragma unroll
                for (int j = 0; j < 8; j++)
                    acc[i][j] = fmaf(a[i], bb[j], acc[i][j]);
        }
        __syncthreads();
    }

    float bv[8];
#pragma unroll
    for (int j = 0; j < 8; j++)
        bv[j] = HAS_BIAS ? bias[colB + tx * 8 + j] : 0.f;
#pragma unroll
    for (int i = 0; i < 8; i++) {
        float o[8];
#pragma unroll
        for (int j = 0; j < 8; j++) {
            float v = acc[i][j] + bv[j];
            o[j] = DO_ELU ? elu1(v) : v;
        }
        float* cp = C + (size_t)(row0 + ty * 8 + i) * ldc + col0 + tx * 8;
        *(float4*)(cp)     = *(float4*)&o[0];
        *(float4*)(cp + 4) = *(float4*)&o[4];
    }
}

// ---------------------------------------------------------------------------
__global__ void __launch_bounds__(256)
edge2node_kernel(const float* __restrict__ x2, float* __restrict__ inc)
{
    int row = blockIdx.x;
    int c   = threadIdx.x;
    int b   = row / N_NODE;
    int n   = row - b * N_NODE;
    const float* base = x2 + ((size_t)(b * N_EDGE + n * 99)) * HID + c;
    float s = 0.f;
#pragma unroll 4
    for (int t = 0; t < 99; t++) s += base[(size_t)t * HID];
    inc[(size_t)row * HID + c] = s * (1.0f / (float)N_EDGE);
}

__global__ void __launch_bounds__(512)
zero_stats_kernel(float* __restrict__ psum, float* __restrict__ psq)
{
    int t = threadIdx.x;
    if (t < 256) psum[t] = 0.f;
    else         psq[t - 256] = 0.f;
}

__global__ void __launch_bounds__(256)
bn_final_kernel(const float* __restrict__ psum, const float* __restrict__ psq,
                const float* __restrict__ gamma, const float* __restrict__ beta,
                const float* __restrict__ fcW, const float* __restrict__ fcb,
                float* __restrict__ Wp, float* __restrict__ bp)
{
    int c = threadIdx.x;
    float s = psum[c];
    float q = psq[c];
    const float invM = 1.0f / (float)ROWS_EDGE;
    float m   = s * invM;
    float var = q * invM - m * m;
    float sc  = gamma[c] * rsqrtf(var + 1e-5f);
    float sh  = beta[c] - m * sc;
    float w0  = fcW[c * 2 + 0], w1 = fcW[c * 2 + 1];
    Wp[c]       = sc * w0;
    Wp[HID + c] = sc * w1;

    __shared__ float r0[256], r1[256];
    r0[c] = sh * w0;
    r1[c] = sh * w1;
    __syncthreads();
    for (int off = 128; off > 0; off >>= 1) {
        if (c < off) { r0[c] += r0[c + off]; r1[c] += r1[c + off]; }
        __syncthreads();
    }
    if (c == 0) {
        bp[0] = r0[0] + fcb[0];
        bp[1] = r1[0] + fcb[1];
    }
}

__global__ void __launch_bounds__(256)
out_kernel(const float* __restrict__ x4, const float* __restrict__ Wp,
           const float* __restrict__ bp, float* __restrict__ out)
{
    __shared__ float w0[256], w1[256];
    __shared__ float bsh[2];
    int tid = threadIdx.x;
    w0[tid] = Wp[tid];
    w1[tid] = Wp[256 + tid];
    if (tid < 2) bsh[tid] = bp[tid];
    __syncthreads();

    int warp = tid >> 5, lane = tid & 31;
    size_t row = (size_t)blockIdx.x * 8 + warp;
    const float4* xr = (const float4*)(x4 + row * HID);
    float s0 = 0.f, s1 = 0.f;
#pragma unroll
    for (int u = 0; u < 2; u++) {
        float4 xv = xr[lane + u * 32];
        int cb = (lane + u * 32) * 4;
        float4 a = *(const float4*)&w0[cb];
        float4 b = *(const float4*)&w1[cb];
        s0 += xv.x * a.x + xv.y * a.y + xv.z * a.z + xv.w * a.w;
        s1 += xv.x * b.x + xv.y * b.y + xv.z * b.z + xv.w * b.w;
    }
#pragma unroll
    for (int off = 16; off; off >>= 1) {
        s0 += __shfl_xor_sync(0xffffffffu, s0, off);
        s1 += __shfl_xor_sync(0xffffffffu, s1, off);
    }
    if (lane == 0) {
        out[row * 2 + 0] = s0 + bsh[0];
        out[row * 2 + 1] = s1 + bsh[1];
    }
}

// ---------------------------------------------------------------------------
extern "C" void kernel_launch(void* const* d_in, const int* in_sizes, int n_in,
                              void* d_out, int out_size)
{
    (void)in_sizes; (void)n_in; (void)out_size;

    const float* x_in = (const float*)d_in[0];
    const float* W1_1 = (const float*)d_in[3];
    const float* b1_1 = (const float*)d_in[4];
    const float* W1_2 = (const float*)d_in[5];
    const float* b1_2 = (const float*)d_in[6];
    const float* W2_1 = (const float*)d_in[7];
    const float* b2_1 = (const float*)d_in[8];
    const float* W2_2 = (const float*)d_in[9];
    const float* b2_2 = (const float*)d_in[10];
    const float* W3_1 = (const float*)d_in[11];
    const float* b3_1 = (const float*)d_in[12];
    const float* W3_2 = (const float*)d_in[13];
    const float* b3_2 = (const float*)d_in[14];
    const float* W4_1 = (const float*)d_in[15];
    const float* b4_1 = (const float*)d_in[16];
    const float* W4_2 = (const float*)d_in[17];
    const float* b4_2 = (const float*)d_in[18];
    const float* bn_g = (const float*)d_in[19];
    const float* bn_b = (const float*)d_in[20];
    const float* fcW  = (const float*)d_in[21];
    const float* fcb  = (const float*)d_in[22];
    float* out = (float*)d_out;

    float* scratch = nullptr;
    cudaGetSymbolAddress((void**)&scratch, g_scratch);

    float* h1a  = scratch + OFF_H1A;
    float* h1   = scratch + OFF_H1;
    float* SR   = scratch + OFF_SR;      // [3200,512]: send | recv halves
    float* inc  = scratch + OFF_INC;
    float* h3a  = scratch + OFF_H3A;
    float* h3   = scratch + OFF_H3;
    float* AC   = scratch + OFF_AC;      // [3200,512]
    float* x2   = scratch + OFF_X2;
    float* skip = scratch + OFF_SKIP;
    float* x4   = scratch + OFF_X4;
    float* psum = scratch + OFF_PSUM;
    float* psq  = scratch + OFF_PSQ;
    float* Wp   = scratch + OFF_WP;
    float* bpv  = scratch + OFF_BP;
    uint32_t* WBu = (uint32_t*)(scratch + OFF_WB);
    uint32_t* WB2 = WBu;                 // frag images: W2_2
    uint32_t* WB4 = WBu + 65536;         // W4_2
    uint32_t* WBS = WBu + 131072;        // W4_1[512:768]

    static bool attr_done = false;
    if (!attr_done) {
        cudaFuncSetAttribute((const void*)edge_tf32_kernel<0>,
                             cudaFuncAttributeMaxDynamicSharedMemorySize, EDGE_SMEM_BYTES);
        cudaFuncSetAttribute((const void*)edge_tf32_kernel<1>,
                             cudaFuncAttributeMaxDynamicSharedMemorySize, EDGE_SMEM_BYTES);
        cudaFuncSetAttribute((const void*)edge_tf32_kernel<2>,
                             cudaFuncAttributeMaxDynamicSharedMemorySize, EDGE_SMEM_BYTES);
        attr_done = true;
    }

    dim3 blk(256);
    dim3 gn(ROWS_NODE / 128, 2);        // (25, 2)
    dim3 gw(ROWS_NODE / 128, 4);        // (25, 4)  merged wide-N
    const int gedge = ROWS_EDGE / 128;  // 2475

    // fragment-order the 3 big weight matrices (tf32)
    wprep_kernel<<<768, blk>>>(W2_2, W4_2, W4_1 + 512 * 256, WBu);
    zero_stats_kernel<<<1, 512>>>(psum, psq);

    // mlp1 (exact fp32)
    gemm_kernel<8,  true,  true ><<<gn, blk>>>(x_in, W1_1, nullptr, b1_1, h1a,
                                               K_IN, HID, HID);
    gemm_kernel<16, true,  true ><<<gn, blk>>>(h1a, W1_2, nullptr, b1_2, h1,
                                               HID, HID, HID);
    // merged per-node halves of mlp2 layer-1 -> SR  (exact fp32)
    gemm_kernel<16, false, false><<<gw, blk>>>(h1, W2_1, W2_1 + 65536, nullptr, SR,
                                               HID, HID, 512);
    // mlp2 fused (gather + elu + layer-2) -> x2   [tf32 MMA]
    edge_tf32_kernel<1><<<gedge, blk, EDGE_SMEM_BYTES>>>(
        SR, SR + 256, nullptr, b2_1, WB2, b2_2, x2, 512, nullptr, nullptr);
    // skip part of mlp4 layer-1: x2 @ W4_1[512:768]   [tf32 MMA]
    edge_tf32_kernel<0><<<gedge, blk, EDGE_SMEM_BYTES>>>(
        x2, nullptr, nullptr, nullptr, WBS, nullptr, skip, 0, nullptr, nullptr);
    // edge2node
    edge2node_kernel<<<ROWS_NODE, blk>>>(x2, inc);
    // mlp3 (exact fp32)
    gemm_kernel<16, true,  true ><<<gn, blk>>>(inc, W3_1, nullptr, b3_1, h3a,
                                               HID, HID, HID);
    gemm_kernel<16, true,  true ><<<gn, blk>>>(h3a, W3_2, nullptr, b3_2, h3,
                                               HID, HID, HID);
    // merged per-node halves of mlp4 layer-1 -> AC  (exact fp32)
    gemm_kernel<16, false, false><<<gw, blk>>>(h3, W4_1, W4_1 + 65536, nullptr, AC,
                                               HID, HID, 512);
    // mlp4 fused (gather + skip + elu + layer-2) -> x4, + BN partials [tf32 MMA]
    edge_tf32_kernel<2><<<gedge, blk, EDGE_SMEM_BYTES>>>(
        AC, AC + 256, skip, b4_1, WB4, b4_2, x4, 512, psum, psq);
    // batchnorm finalize + fc fold
    bn_final_kernel<<<1, blk>>>(psum, psq, bn_g, bn_b, fcW, fcb, Wp, bpv);
    // final GEMV
    out_kernel<<<ROWS_EDGE / 8, blk>>>(x4, Wp, bpv, out);
}

// round 16
// speedup vs baseline: 1.4662x; 1.4662x over previous
#include <cuda_runtime.h>
#include <math.h>
#include <stdint.h>

// ---------------------------------------------------------------------------
// MLPEncoder — round 15: recovery to proven R11 edge kernels + node merges.
//  * edge tf32 kernels: byte-identical to the 2137us R11 version (+ ldP arg)
//  * node GEMM pairs merged into wide-N single launches (SR, AC)
//  * BN stats back to deterministic two-pass (no epilogue fusion)
// ---------------------------------------------------------------------------

#define B_SZ    32
#define N_NODE  100
#define N_EDGE  9900
#define HID     256
#define K_IN    200
#define ROWS_NODE (B_SZ * N_NODE)          // 3200
#define ROWS_EDGE (B_SZ * N_EDGE)          // 316800
#define NPART   990
#define ROWS_PER_PART (ROWS_EDGE / NPART)  // 320

// scratch layout (float offsets)
#define OFF_H1A  0ull
#define OFF_H1   819200ull
#define OFF_SR   1638400ull                // merged S|R  [3200,512]
#define OFF_INC  3276800ull
#define OFF_H3A  4096000ull
#define OFF_H3   4915200ull
#define OFF_AC   5734400ull                // merged A3|C3 [3200,512]
#define OFF_X2   7372800ull
#define OFF_SKIP 88473600ull
#define OFF_X4   169574400ull
#define OFF_PSUM 250675200ull
#define OFF_PSQ  250928640ull
#define OFF_WP   251182080ull
#define OFF_BP   251182592ull
#define OFF_WT   251182720ull              // 3 x 65536 tf32-rounded weights
#define SCRATCH_FLOATS 251379328ull

__device__ __align__(256) float g_scratch[SCRATCH_FLOATS];

__device__ __forceinline__ float elu1(float x) {
    return x > 0.f ? x : expm1f(x);
}

// ---------------- tf32 / mma helpers ----------------
__device__ __forceinline__ uint32_t f2tf(float x) {
    uint32_t r;
    asm("cvt.rna.tf32.f32 %0, %1;" : "=r"(r) : "f"(x));
    return r;
}

__device__ __forceinline__ void mma8(float* d, const uint32_t* a, const uint32_t* b) {
    asm volatile(
        "mma.sync.aligned.m16n8k8.row.col.f32.tf32.tf32.f32 "
        "{%0,%1,%2,%3}, {%4,%5,%6,%7}, {%8,%9}, {%0,%1,%2,%3};"
        : "+f"(d[0]), "+f"(d[1]), "+f"(d[2]), "+f"(d[3])
        : "r"(a[0]), "r"(a[1]), "r"(a[2]), "r"(a[3]), "r"(b[0]), "r"(b[1]));
}

__device__ __forceinline__ uint32_t smem_u32(const void* p) {
    uint32_t a;
    asm("{ .reg .u64 t; cvta.to.shared.u64 t, %1; cvt.u32.u64 %0, t; }"
        : "=r"(a) : "l"(p));
    return a;
}

__device__ __forceinline__ void cp16(uint32_t saddr, const void* g) {
    asm volatile("cp.async.ca.shared.global [%0], [%1], 16;"
                 :: "r"(saddr), "l"(g) : "memory");
}

// ---------------------------------------------------------------------------
// tf32 MMA GEMM over edge rows (R11-proven): C = epi(A'[.,256] @ Bt[256,256])
//  MODE 0: A' = Ap rows (plain, stride 256);         epi: raw
//  MODE 1: A' = elu(Ap[sJ] + Qp[sI] + preb);         epi: elu(.+bias2)
//  MODE 2: A' = elu(Ap[sJ] + Qp[sI] + extra + preb); epi: elu(.+bias2)
// CTA tile 128x256, BK=32, 8 warps @ 64x64, double-buffered smem.
// ---------------------------------------------------------------------------
#define AS_STRIDE 144
#define BS_STRIDE 264
#define AS_SZ (32 * AS_STRIDE)            // 4608 u32
#define BS_SZ (32 * BS_STRIDE)            // 8448 u32
#define BUF_SZ (AS_SZ + BS_SZ)            // 13056 u32
#define EDGE_SMEM_BYTES (2 * BUF_SZ * 4)  // 104448 B

template <int MODE>
__global__ void __launch_bounds__(256, 1)
edge_tf32_kernel(const float* __restrict__ Ap, const float* __restrict__ Qp,
                 const float* __restrict__ extra, const float* __restrict__ preb,
                 const float* __restrict__ Bt, const float* __restrict__ bias2,
                 float* __restrict__ C, int ldP)
{
    extern __shared__ uint32_t dsm[];
    __shared__ int   sJ[128], sI[128];
    __shared__ float sPreb[256];

    const int tid  = threadIdx.x;
    const int row0 = blockIdx.x * 128;
    const int warp = tid >> 5, lane = tid & 31;
    const int wm = warp >> 2, wn = warp & 3;
    const int g  = lane >> 2, tg = lane & 3;

    if (MODE >= 1) {
        if (tid < 128) {
            int r  = row0 + tid;
            int b  = r / N_EDGE;
            int e  = r - b * N_EDGE;
            int i  = e / 99;
            int jr = e - i * 99;
            int j  = jr + (jr >= i);
            sJ[tid] = (b * N_NODE + j) * ldP;
            sI[tid] = (b * N_NODE + i) * ldP;
        }
        sPreb[tid] = preb[tid];
        __syncthreads();
    }

    const int arow  = tid >> 1;
    const int kh    = (tid & 1) * 16;
    const int aslot = (arow & 0x70) + ((arow & 7) << 1) + ((arow >> 3) & 1);

    const float* pJ = nullptr;
    const float* pI = nullptr;
    const float* pE = nullptr;
    const float* pA = nullptr;
    if (MODE >= 1) {
        pJ = Ap + sJ[arow];
        pI = Qp + sI[arow];
        if (MODE == 2) pE = extra + (size_t)(row0 + arow) * HID;
    } else {
        pA = Ap + (size_t)(row0 + arow) * HID;
    }

    const uint32_t smem0 = smem_u32(dsm);
    float va[16];

    auto loadA = [&](int t) {
        const int gk = t * 32 + kh;
        if (MODE == 0) {
            const float4* ap = (const float4*)(pA + gk);
#pragma unroll
            for (int q = 0; q < 4; q++) {
                float4 v = ap[q];
                va[4 * q + 0] = v.x; va[4 * q + 1] = v.y;
                va[4 * q + 2] = v.z; va[4 * q + 3] = v.w;
            }
        } else {
            const float4* jp = (const float4*)(pJ + gk);
            const float4* ip = (const float4*)(pI + gk);
#pragma unroll
            for (int q = 0; q < 4; q++) {
                float4 a = jp[q], b = ip[q];
                float4 s;
                s.x = a.x + b.x; s.y = a.y + b.y;
                s.z = a.z + b.z; s.w = a.w + b.w;
                if (MODE == 2) {
                    float4 e = ((const float4*)(pE + gk))[q];
                    s.x += e.x; s.y += e.y; s.z += e.z; s.w += e.w;
                }
                va[4 * q + 0] = s.x; va[4 * q + 1] = s.y;
                va[4 * q + 2] = s.z; va[4 * q + 3] = s.w;
            }
#pragma unroll
            for (int x = 0; x < 16; x++)
                va[x] = elu1(va[x] + sPreb[gk + x]);
        }
    };

    auto storeA = [&](int buf) {
        uint32_t* dst = dsm + buf * BUF_SZ;
#pragma unroll
        for (int x = 0; x < 16; x++)
            dst[(kh + x) * AS_STRIDE + aslot] = f2tf(va[x]);
    };

    auto loadB = [&](int t, int buf) {
        const uint32_t sb = smem0 + (uint32_t)(buf * BUF_SZ + AS_SZ) * 4;
        const float* src = Bt + (size_t)(t * 32) * HID;
#pragma unroll
        for (int u = 0; u < 8; u++) {
            int idx = tid + u * 256;
            int kk  = idx >> 6;
            int c4  = (idx & 63) << 2;
            cp16(sb + (uint32_t)(kk * BS_STRIDE + c4) * 4, src + kk * HID + c4);
        }
        asm volatile("cp.async.commit_group;" ::: "memory");
    };

    // preload chunk 0
    loadA(0);
    loadB(0, 0);
    storeA(0);
    asm volatile("cp.async.wait_group 0;" ::: "memory");
    __syncthreads();

    float acc[4][8][4];
#pragma unroll
    for (int mt = 0; mt < 4; mt++)
#pragma unroll
        for (int nt = 0; nt < 8; nt++)
#pragma unroll
            for (int q = 0; q < 4; q++) acc[mt][nt][q] = 0.f;

    for (int t = 0; t < 8; t++) {
        const int cur = t & 1, nxt = cur ^ 1;
        if (t < 7) {
            loadB(t + 1, nxt);
            loadA(t + 1);
        }
        const uint32_t* As = dsm + cur * BUF_SZ;
        const uint32_t* Bs = dsm + cur * BUF_SZ + AS_SZ;
#pragma unroll
        for (int ks = 0; ks < 4; ks++) {
            const int kr0 = ks * 8 + tg;
            uint32_t af[4][4];
#pragma unroll
            for (int mt = 0; mt < 4; mt++) {
                const int mb = wm * 64 + mt * 16 + 2 * g;
                uint2 lo = *(const uint2*)&As[kr0 * AS_STRIDE + mb];
                uint2 hi = *(const uint2*)&As[(kr0 + 4) * AS_STRIDE + mb];
                af[mt][0] = lo.x; af[mt][1] = lo.y;
                af[mt][2] = hi.x; af[mt][3] = hi.y;
            }
            uint32_t bf[8][2];
#pragma unroll
            for (int nt = 0; nt < 8; nt++) {
                const int nb = wn * 64 + nt * 8 + g;
                bf[nt][0] = Bs[kr0 * BS_STRIDE + nb];
                bf[nt][1] = Bs[(kr0 + 4) * BS_STRIDE + nb];
            }
#pragma unroll
            for (int mt = 0; mt < 4; mt++)
#pragma unroll
                for (int nt = 0; nt < 8; nt++)
                    mma8(acc[mt][nt], af[mt], bf[nt]);
        }
        if (t < 7) {
            storeA(nxt);
            asm volatile("cp.async.wait_group 0;" ::: "memory");
            __syncthreads();
        }
    }

    // epilogue
    float bcol0[8], bcol1[8];
    if (MODE >= 1) {
#pragma unroll
        for (int nt = 0; nt < 8; nt++) {
            const int col = wn * 64 + nt * 8 + tg * 2;
            bcol0[nt] = bias2[col];
            bcol1[nt] = bias2[col + 1];
        }
    }
#pragma unroll
    for (int mt = 0; mt < 4; mt++) {
        const int ra = row0 + wm * 64 + mt * 16 + g;
#pragma unroll
        for (int nt = 0; nt < 8; nt++) {
            const int col = wn * 64 + nt * 8 + tg * 2;
            float2 o0, o1;
            if (MODE == 0) {
                o0.x = acc[mt][nt][0]; o0.y = acc[mt][nt][1];
                o1.x = acc[mt][nt][2]; o1.y = acc[mt][nt][3];
            } else {
                o0.x = elu1(acc[mt][nt][0] + bcol0[nt]);
                o0.y = elu1(acc[mt][nt][1] + bcol1[nt]);
                o1.x = elu1(acc[mt][nt][2] + bcol0[nt]);
                o1.y = elu1(acc[mt][nt][3] + bcol1[nt]);
            }
            *(float2*)(C + (size_t)ra * HID + col)       = o0;
            *(float2*)(C + (size_t)(ra + 8) * HID + col) = o1;
        }
    }
}

// ---------------------------------------------------------------------------
// Pre-round the 3 big weight matrices to tf32 (rna), row-major (R11 layout).
// ---------------------------------------------------------------------------
__global__ void __launch_bounds__(256)
wprep_kernel(const float* __restrict__ W2, const float* __restrict__ W4,
             const float* __restrict__ Ws, float* __restrict__ out)
{
    int i = blockIdx.x * 256 + threadIdx.x;   // grid 768 -> 196608
    const float* src;
    int j = i;
    if (i < 65536)        { src = W2; }
    else if (i < 131072)  { src = W4; j = i - 65536; }
    else                  { src = Ws; j = i - 131072; }
    out[i] = __uint_as_float(f2tf(src[j]));
}

// ---------------------------------------------------------------------------
// Generic fp32 tiled GEMM (node-level, exact). Bm_hi: optional second weight
// block for merged wide-N calls (col0 >= 256 reads Bm_hi at col0-256).
// ---------------------------------------------------------------------------
template <int BK, bool DO_ELU, bool HAS_BIAS>
__global__ void __launch_bounds__(256, 2)
gemm_kernel(const float* __restrict__ A, const float* __restrict__ Bm,
            const float* __restrict__ Bm_hi,
            const float* __restrict__ bias, float* __restrict__ C,
            int K, int ldb, int ldc)
{
    const int tid  = threadIdx.x;
    const int tx   = tid & 15;
    const int ty   = tid >> 4;
    const int row0 = blockIdx.x * 128;
    const int col0 = blockIdx.y * 128;
    int colB = col0;
    const float* B = Bm;
    if (Bm_hi != nullptr && col0 >= 256) { B = Bm_hi; colB = col0 - 256; }

    __shared__ float As[BK][132];
    __shared__ float Bs[BK][128];

    float acc[8][8];
#pragma unroll
    for (int i = 0; i < 8; i++)
#pragma unroll
        for (int j = 0; j < 8; j++) acc[i][j] = 0.f;

    const int NT = K / BK;
    for (int t = 0; t < NT; t++) {
        const int k0 = t * BK;
        if constexpr (BK == 8) {
            const int am = tid >> 1, ac = (tid & 1) * 4;
            float4 v = *(const float4*)(A + (size_t)(row0 + am) * K + k0 + ac);
            As[ac + 0][am] = v.x; As[ac + 1][am] = v.y;
            As[ac + 2][am] = v.z; As[ac + 3][am] = v.w;
            const int bk = tid >> 5, bn = (tid & 31) * 4;
            *(float4*)&Bs[bk][bn] =
                *(const float4*)(B + (size_t)(k0 + bk) * ldb + colB + bn);
        } else {
            const int am = tid >> 1, ac = (tid & 1) * 8;
            const float* ap = A + (size_t)(row0 + am) * K + k0 + ac;
            float4 v0 = *(const float4*)(ap);
            float4 v1 = *(const float4*)(ap + 4);
            As[ac + 0][am] = v0.x; As[ac + 1][am] = v0.y;
            As[ac + 2][am] = v0.z; As[ac + 3][am] = v0.w;
            As[ac + 4][am] = v1.x; As[ac + 5][am] = v1.y;
            As[ac + 6][am] = v1.z; As[ac + 7][am] = v1.w;
            const int bk = tid >> 4, bn = (tid & 15) * 8;
            const float* bp = B + (size_t)(k0 + bk) * ldb + colB + bn;
            *(float4*)&Bs[bk][bn]     = *(const float4*)(bp);
            *(float4*)&Bs[bk][bn + 4] = *(const float4*)(bp + 4);
        }
        __syncthreads();
#pragma unroll
        for (int k = 0; k < BK; k++) {
            float a[8], bb[8];
            *(float4*)&a[0]  = *(const float4*)&As[k][ty * 8];
            *(float4*)&a[4]  = *(const float4*)&As[k][ty * 8 + 4];
            *(float4*)&bb[0] = *(const float4*)&Bs[k][tx * 8];
            *(float4*)&bb[4] = *(const float4*)&Bs[k][tx * 8 + 4];
#pragma unroll
            for (int i = 0; i < 8; i++)
#pragma unroll
                for (int j = 0; j < 8; j++)
                    acc[i][j] = fmaf(a[i], bb[j], acc[i][j]);
        }
        __syncthreads();
    }

    float bv[8];
#pragma unroll
    for (int j = 0; j < 8; j++)
        bv[j] = HAS_BIAS ? bias[colB + tx * 8 + j] : 0.f;
#pragma unroll
    for (int i = 0; i < 8; i++) {
        float o[8];
#pragma unroll
        for (int j = 0; j < 8; j++) {
            float v = acc[i][j] + bv[j];
            o[j] = DO_ELU ? elu1(v) : v;
        }
        float* cp = C + (size_t)(row0 + ty * 8 + i) * ldc + col0 + tx * 8;
        *(float4*)(cp)     = *(float4*)&o[0];
        *(float4*)(cp + 4) = *(float4*)&o[4];
    }
}

// ---------------------------------------------------------------------------
__global__ void __launch_bounds__(256)
edge2node_kernel(const float* __restrict__ x2, float* __restrict__ inc)
{
    int row = blockIdx.x;
    int c   = threadIdx.x;
    int b   = row / N_NODE;
    int n   = row - b * N_NODE;
    const float* base = x2 + ((size_t)(b * N_EDGE + n * 99)) * HID + c;
    float s = 0.f;
#pragma unroll 4
    for (int t = 0; t < 99; t++) s += base[(size_t)t * HID];
    inc[(size_t)row * HID + c] = s * (1.0f / (float)N_EDGE);
}

// ---------------------------------------------------------------------------
// BN statistics: deterministic two-pass partial sums, then finalize + fold fc
// ---------------------------------------------------------------------------
__global__ void __launch_bounds__(256)
bn_partial_kernel(const float* __restrict__ x4,
                  float* __restrict__ psum, float* __restrict__ psq)
{
    int c = threadIdx.x, g = blockIdx.x;
    const float* base = x4 + (size_t)g * ROWS_PER_PART * HID + c;
    float s = 0.f, q = 0.f;
    for (int r = 0; r < ROWS_PER_PART; r++) {
        float v = base[(size_t)r * HID];
        s += v;
        q = fmaf(v, v, q);
    }
    psum[g * HID + c] = s;
    psq [g * HID + c] = q;
}

__global__ void __launch_bounds__(256)
bn_final_kernel(const float* __restrict__ psum, const float* __restrict__ psq,
                const float* __restrict__ gamma, const float* __restrict__ beta,
                const float* __restrict__ fcW, const float* __restrict__ fcb,
                float* __restrict__ Wp, float* __restrict__ bp)
{
    int c = threadIdx.x;
    float s = 0.f, q = 0.f;
    for (int g = 0; g < NPART; g++) {
        s += psum[g * HID + c];
        q += psq [g * HID + c];
    }
    const float invM = 1.0f / (float)ROWS_EDGE;
    float m   = s * invM;
    float var = q * invM - m * m;
    float sc  = gamma[c] * rsqrtf(var + 1e-5f);
    float sh  = beta[c] - m * sc;
    float w0  = fcW[c * 2 + 0], w1 = fcW[c * 2 + 1];
    Wp[c]       = sc * w0;
    Wp[HID + c] = sc * w1;

    __shared__ float r0[256], r1[256];
    r0[c] = sh * w0;
    r1[c] = sh * w1;
    __syncthreads();
    for (int off = 128; off > 0; off >>= 1) {
        if (c < off) { r0[c] += r0[c + off]; r1[c] += r1[c + off]; }
        __syncthreads();
    }
    if (c == 0) {
        bp[0] = r0[0] + fcb[0];
        bp[1] = r1[0] + fcb[1];
    }
}

__global__ void __launch_bounds__(256)
out_kernel(const float* __restrict__ x4, const float* __restrict__ Wp,
           const float* __restrict__ bp, float* __restrict__ out)
{
    __shared__ float w0[256], w1[256];
    __shared__ float bsh[2];
    int tid = threadIdx.x;
    w0[tid] = Wp[tid];
    w1[tid] = Wp[256 + tid];
    if (tid < 2) bsh[tid] = bp[tid];
    __syncthreads();

    int warp = tid >> 5, lane = tid & 31;
    size_t row = (size_t)blockIdx.x * 8 + warp;
    const float4* xr = (const float4*)(x4 + row * HID);
    float s0 = 0.f, s1 = 0.f;
#pragma unroll
    for (int u = 0; u < 2; u++) {
        float4 xv = xr[lane + u * 32];
        int cb = (lane + u * 32) * 4;
        float4 a = *(const float4*)&w0[cb];
        float4 b = *(const float4*)&w1[cb];
        s0 += xv.x * a.x + xv.y * a.y + xv.z * a.z + xv.w * a.w;
        s1 += xv.x * b.x + xv.y * b.y + xv.z * b.z + xv.w * b.w;
    }
#pragma unroll
    for (int off = 16; off; off >>= 1) {
        s0 += __shfl_xor_sync(0xffffffffu, s0, off);
        s1 += __shfl_xor_sync(0xffffffffu, s1, off);
    }
    if (lane == 0) {
        out[row * 2 + 0] = s0 + bsh[0];
        out[row * 2 + 1] = s1 + bsh[1];
    }
}

// ---------------------------------------------------------------------------
extern "C" void kernel_launch(void* const* d_in, const int* in_sizes, int n_in,
                              void* d_out, int out_size)
{
    (void)in_sizes; (void)n_in; (void)out_size;

    const float* x_in = (const float*)d_in[0];
    const float* W1_1 = (const float*)d_in[3];
    const float* b1_1 = (const float*)d_in[4];
    const float* W1_2 = (const float*)d_in[5];
    const float* b1_2 = (const float*)d_in[6];
    const float* W2_1 = (const float*)d_in[7];
    const float* b2_1 = (const float*)d_in[8];
    const float* W2_2 = (const float*)d_in[9];
    const float* b2_2 = (const float*)d_in[10];
    const float* W3_1 = (const float*)d_in[11];
    const float* b3_1 = (const float*)d_in[12];
    const float* W3_2 = (const float*)d_in[13];
    const float* b3_2 = (const float*)d_in[14];
    const float* W4_1 = (const float*)d_in[15];
    const float* b4_1 = (const float*)d_in[16];
    const float* W4_2 = (const float*)d_in[17];
    const float* b4_2 = (const float*)d_in[18];
    const float* bn_g = (const float*)d_in[19];
    const float* bn_b = (const float*)d_in[20];
    const float* fcW  = (const float*)d_in[21];
    const float* fcb  = (const float*)d_in[22];
    float* out = (float*)d_out;

    float* scratch = nullptr;
    cudaGetSymbolAddress((void**)&scratch, g_scratch);

    float* h1a  = scratch + OFF_H1A;
    float* h1   = scratch + OFF_H1;
    float* SR   = scratch + OFF_SR;      // [3200,512]: send | recv halves
    float* inc  = scratch + OFF_INC;
    float* h3a  = scratch + OFF_H3A;
    float* h3   = scratch + OFF_H3;
    float* AC   = scratch + OFF_AC;      // [3200,512]
    float* x2   = scratch + OFF_X2;
    float* skip = scratch + OFF_SKIP;
    float* x4   = scratch + OFF_X4;
    float* psum = scratch + OFF_PSUM;
    float* psq  = scratch + OFF_PSQ;
    float* Wp   = scratch + OFF_WP;
    float* bpv  = scratch + OFF_BP;
    float* WT2  = scratch + OFF_WT;            // tf32(W2_2)
    float* WT4  = scratch + OFF_WT + 65536;    // tf32(W4_2)
    float* WTS  = scratch + OFF_WT + 131072;   // tf32(W4_1[512:768])

    static bool attr_done = false;
    if (!attr_done) {
        cudaFuncSetAttribute((const void*)edge_tf32_kernel<0>,
                             cudaFuncAttributeMaxDynamicSharedMemorySize, EDGE_SMEM_BYTES);
        cudaFuncSetAttribute((const void*)edge_tf32_kernel<1>,
                             cudaFuncAttributeMaxDynamicSharedMemorySize, EDGE_SMEM_BYTES);
        cudaFuncSetAttribute((const void*)edge_tf32_kernel<2>,
                             cudaFuncAttributeMaxDynamicSharedMemorySize, EDGE_SMEM_BYTES);
        attr_done = true;
    }

    dim3 blk(256);
    dim3 gn(ROWS_NODE / 128, 2);        // (25, 2)
    dim3 gw(ROWS_NODE / 128, 4);        // (25, 4)  merged wide-N
    const int gedge = ROWS_EDGE / 128;  // 2475

    // tf32-round the 3 big weight matrices (row-major, R11 layout)
    wprep_kernel<<<768, blk>>>(W2_2, W4_2, W4_1 + 512 * 256, scratch + OFF_WT);

    // mlp1 (exact fp32)
    gemm_kernel<8,  true,  true ><<<gn, blk>>>(x_in, W1_1, nullptr, b1_1, h1a,
                                               K_IN, HID, HID);
    gemm_kernel<16, true,  true ><<<gn, blk>>>(h1a, W1_2, nullptr, b1_2, h1,
                                               HID, HID, HID);
    // merged per-node halves of mlp2 layer-1 -> SR  (exact fp32)
    gemm_kernel<16, false, false><<<gw, blk>>>(h1, W2_1, W2_1 + 65536, nullptr, SR,
                                               HID, HID, 512);
    // mlp2 fused (gather + elu + layer-2) -> x2   [tf32 MMA, R11 kernel]
    edge_tf32_kernel<1><<<gedge, blk, EDGE_SMEM_BYTES>>>(
        SR, SR + 256, nullptr, b2_1, WT2, b2_2, x2, 512);
    // skip part of mlp4 layer-1: x2 @ W4_1[512:768]   [tf32 MMA]
    edge_tf32_kernel<0><<<gedge, blk, EDGE_SMEM_BYTES>>>(
        x2, nullptr, nullptr, nullptr, WTS, nullptr, skip, 0);
    // edge2node
    edge2node_kernel<<<ROWS_NODE, blk>>>(x2, inc);
    // mlp3 (exact fp32)
    gemm_kernel<16, true,  true ><<<gn, blk>>>(inc, W3_1, nullptr, b3_1, h3a,
                                               HID, HID, HID);
    gemm_kernel<16, true,  true ><<<gn, blk>>>(h3a, W3_2, nullptr, b3_2, h3,
                                               HID, HID, HID);
    // merged per-node halves of mlp4 layer-1 -> AC  (exact fp32)
    gemm_kernel<16, false, false><<<gw, blk>>>(h3, W4_1, W4_1 + 65536, nullptr, AC,
                                               HID, HID, 512);
    // mlp4 fused (gather + skip + elu + layer-2) -> x4   [tf32 MMA]
    edge_tf32_kernel<2><<<gedge, blk, EDGE_SMEM_BYTES>>>(
        AC, AC + 256, skip, b4_1, WT4, b4_2, x4, 512);
    // batchnorm stats (deterministic two-pass) + fc fold
    bn_partial_kernel<<<NPART, blk>>>(x4, psum, psq);
    bn_final_kernel<<<1, blk>>>(psum, psq, bn_g, bn_b, fcW, fcb, Wp, bpv);
    // final GEMV
    out_kernel<<<ROWS_EDGE / 8, blk>>>(x4, Wp, bpv, out);
}

// round 17
// speedup vs baseline: 1.4725x; 1.0043x over previous
#include <cuda_runtime.h>
#include <math.h>
#include <stdint.h>

// ---------------------------------------------------------------------------
// MLPEncoder — round 16: R15 kernels unchanged; adds stream-level overlap:
//   * wprep (s2)  ||  mlp1 -> SR chain (main), join before edge GEMM 1
//   * node chain edge2node->mlp3->mlp3->AC (s2)  ||  skip GEMM (main),
//     join before edge GEMM 3
// Edge tf32 kernels byte-identical to the proven 2071us version.
// ---------------------------------------------------------------------------

#define B_SZ    32
#define N_NODE  100
#define N_EDGE  9900
#define HID     256
#define K_IN    200
#define ROWS_NODE (B_SZ * N_NODE)          // 3200
#define ROWS_EDGE (B_SZ * N_EDGE)          // 316800
#define NPART   990
#define ROWS_PER_PART (ROWS_EDGE / NPART)  // 320

// scratch layout (float offsets)
#define OFF_H1A  0ull
#define OFF_H1   819200ull
#define OFF_SR   1638400ull                // merged S|R  [3200,512]
#define OFF_INC  3276800ull
#define OFF_H3A  4096000ull
#define OFF_H3   4915200ull
#define OFF_AC   5734400ull                // merged A3|C3 [3200,512]
#define OFF_X2   7372800ull
#define OFF_SKIP 88473600ull
#define OFF_X4   169574400ull
#define OFF_PSUM 250675200ull
#define OFF_PSQ  250928640ull
#define OFF_WP   251182080ull
#define OFF_BP   251182592ull
#define OFF_WT   251182720ull              // 3 x 65536 tf32-rounded weights
#define SCRATCH_FLOATS 251379328ull

__device__ __align__(256) float g_scratch[SCRATCH_FLOATS];

__device__ __forceinline__ float elu1(float x) {
    return x > 0.f ? x : expm1f(x);
}

// ---------------- tf32 / mma helpers ----------------
__device__ __forceinline__ uint32_t f2tf(float x) {
    uint32_t r;
    asm("cvt.rna.tf32.f32 %0, %1;" : "=r"(r) : "f"(x));
    return r;
}

__device__ __forceinline__ void mma8(float* d, const uint32_t* a, const uint32_t* b) {
    asm volatile(
        "mma.sync.aligned.m16n8k8.row.col.f32.tf32.tf32.f32 "
        "{%0,%1,%2,%3}, {%4,%5,%6,%7}, {%8,%9}, {%0,%1,%2,%3};"
        : "+f"(d[0]), "+f"(d[1]), "+f"(d[2]), "+f"(d[3])
        : "r"(a[0]), "r"(a[1]), "r"(a[2]), "r"(a[3]), "r"(b[0]), "r"(b[1]));
}

__device__ __forceinline__ uint32_t smem_u32(const void* p) {
    uint32_t a;
    asm("{ .reg .u64 t; cvta.to.shared.u64 t, %1; cvt.u32.u64 %0, t; }"
        : "=r"(a) : "l"(p));
    return a;
}

__device__ __forceinline__ void cp16(uint32_t saddr, const void* g) {
    asm volatile("cp.async.ca.shared.global [%0], [%1], 16;"
                 :: "r"(saddr), "l"(g) : "memory");
}

// ---------------------------------------------------------------------------
// tf32 MMA GEMM over edge rows (R11/R15-proven, unchanged)
// ---------------------------------------------------------------------------
#define AS_STRIDE 144
#define BS_STRIDE 264
#define AS_SZ (32 * AS_STRIDE)            // 4608 u32
#define BS_SZ (32 * BS_STRIDE)            // 8448 u32
#define BUF_SZ (AS_SZ + BS_SZ)            // 13056 u32
#define EDGE_SMEM_BYTES (2 * BUF_SZ * 4)  // 104448 B

template <int MODE>
__global__ void __launch_bounds__(256, 1)
edge_tf32_kernel(const float* __restrict__ Ap, const float* __restrict__ Qp,
                 const float* __restrict__ extra, const float* __restrict__ preb,
                 const float* __restrict__ Bt, const float* __restrict__ bias2,
                 float* __restrict__ C, int ldP)
{
    extern __shared__ uint32_t dsm[];
    __shared__ int   sJ[128], sI[128];
    __shared__ float sPreb[256];

    const int tid  = threadIdx.x;
    const int row0 = blockIdx.x * 128;
    const int warp = tid >> 5, lane = tid & 31;
    const int wm = warp >> 2, wn = warp & 3;
    const int g  = lane >> 2, tg = lane & 3;

    if (MODE >= 1) {
        if (tid < 128) {
            int r  = row0 + tid;
            int b  = r / N_EDGE;
            int e  = r - b * N_EDGE;
            int i  = e / 99;
            int jr = e - i * 99;
            int j  = jr + (jr >= i);
            sJ[tid] = (b * N_NODE + j) * ldP;
            sI[tid] = (b * N_NODE + i) * ldP;
        }
        sPreb[tid] = preb[tid];
        __syncthreads();
    }

    const int arow  = tid >> 1;
    const int kh    = (tid & 1) * 16;
    const int aslot = (arow & 0x70) + ((arow & 7) << 1) + ((arow >> 3) & 1);

    const float* pJ = nullptr;
    const float* pI = nullptr;
    const float* pE = nullptr;
    const float* pA = nullptr;
    if (MODE >= 1) {
        pJ = Ap + sJ[arow];
        pI = Qp + sI[arow];
        if (MODE == 2) pE = extra + (size_t)(row0 + arow) * HID;
    } else {
        pA = Ap + (size_t)(row0 + arow) * HID;
    }

    const uint32_t smem0 = smem_u32(dsm);
    float va[16];

    auto loadA = [&](int t) {
        const int gk = t * 32 + kh;
        if (MODE == 0) {
            const float4* ap = (const float4*)(pA + gk);
#pragma unroll
            for (int q = 0; q < 4; q++) {
                float4 v = ap[q];
                va[4 * q + 0] = v.x; va[4 * q + 1] = v.y;
                va[4 * q + 2] = v.z; va[4 * q + 3] = v.w;
            }
        } else {
            const float4* jp = (const float4*)(pJ + gk);
            const float4* ip = (const float4*)(pI + gk);
#pragma unroll
            for (int q = 0; q < 4; q++) {
                float4 a = jp[q], b = ip[q];
                float4 s;
                s.x = a.x + b.x; s.y = a.y + b.y;
                s.z = a.z + b.z; s.w = a.w + b.w;
                if (MODE == 2) {
                    float4 e = ((const float4*)(pE + gk))[q];
                    s.x += e.x; s.y += e.y; s.z += e.z; s.w += e.w;
                }
                va[4 * q + 0] = s.x; va[4 * q + 1] = s.y;
                va[4 * q + 2] = s.z; va[4 * q + 3] = s.w;
            }
#pragma unroll
            for (int x = 0; x < 16; x++)
                va[x] = elu1(va[x] + sPreb[gk + x]);
        }
    };

    auto storeA = [&](int buf) {
        uint32_t* dst = dsm + buf * BUF_SZ;
#pragma unroll
        for (int x = 0; x < 16; x++)
            dst[(kh + x) * AS_STRIDE + aslot] = f2tf(va[x]);
    };

    auto loadB = [&](int t, int buf) {
        const uint32_t sb = smem0 + (uint32_t)(buf * BUF_SZ + AS_SZ) * 4;
        const float* src = Bt + (size_t)(t * 32) * HID;
#pragma unroll
        for (int u = 0; u < 8; u++) {
            int idx = tid + u * 256;
            int kk  = idx >> 6;
            int c4  = (idx & 63) << 2;
            cp16(sb + (uint32_t)(kk * BS_STRIDE + c4) * 4, src + kk * HID + c4);
        }
        asm volatile("cp.async.commit_group;" ::: "memory");
    };

    // preload chunk 0
    loadA(0);
    loadB(0, 0);
    storeA(0);
    asm volatile("cp.async.wait_group 0;" ::: "memory");
    __syncthreads();

    float acc[4][8][4];
#pragma unroll
    for (int mt = 0; mt < 4; mt++)
#pragma unroll
        for (int nt = 0; nt < 8; nt++)
#pragma unroll
            for (int q = 0; q < 4; q++) acc[mt][nt][q] = 0.f;

    for (int t = 0; t < 8; t++) {
        const int cur = t & 1, nxt = cur ^ 1;
        if (t < 7) {
            loadB(t + 1, nxt);
            loadA(t + 1);
        }
        const uint32_t* As = dsm + cur * BUF_SZ;
        const uint32_t* Bs = dsm + cur * BUF_SZ + AS_SZ;
#pragma unroll
        for (int ks = 0; ks < 4; ks++) {
            const int kr0 = ks * 8 + tg;
            uint32_t af[4][4];
#pragma unroll
            for (int mt = 0; mt < 4; mt++) {
                const int mb = wm * 64 + mt * 16 + 2 * g;
                uint2 lo = *(const uint2*)&As[kr0 * AS_STRIDE + mb];
                uint2 hi = *(const uint2*)&As[(kr0 + 4) * AS_STRIDE + mb];
                af[mt][0] = lo.x; af[mt][1] = lo.y;
                af[mt][2] = hi.x; af[mt][3] = hi.y;
            }
            uint32_t bf[8][2];
#pragma unroll
            for (int nt = 0; nt < 8; nt++) {
                const int nb = wn * 64 + nt * 8 + g;
                bf[nt][0] = Bs[kr0 * BS_STRIDE + nb];
                bf[nt][1] = Bs[(kr0 + 4) * BS_STRIDE + nb];
            }
#pragma unroll
            for (int mt = 0; mt < 4; mt++)
#pragma unroll
                for (int nt = 0; nt < 8; nt++)
                    mma8(acc[mt][nt], af[mt], bf[nt]);
        }
        if (t < 7) {
            storeA(nxt);
            asm volatile("cp.async.wait_group 0;" ::: "memory");
            __syncthreads();
        }
    }

    // epilogue
    float bcol0[8], bcol1[8];
    if (MODE >= 1) {
#pragma unroll
        for (int nt = 0; nt < 8; nt++) {
            const int col = wn * 64 + nt * 8 + tg * 2;
            bcol0[nt] = bias2[col];
            bcol1[nt] = bias2[col + 1];
        }
    }
#pragma unroll
    for (int mt = 0; mt < 4; mt++) {
        const int ra = row0 + wm * 64 + mt * 16 + g;
#pragma unroll
        for (int nt = 0; nt < 8; nt++) {
            const int col = wn * 64 + nt * 8 + tg * 2;
            float2 o0, o1;
            if (MODE == 0) {
                o0.x = acc[mt][nt][0]; o0.y = acc[mt][nt][1];
                o1.x = acc[mt][nt][2]; o1.y = acc[mt][nt][3];
            } else {
                o0.x = elu1(acc[mt][nt][0] + bcol0[nt]);
                o0.y = elu1(acc[mt][nt][1] + bcol1[nt]);
                o1.x = elu1(acc[mt][nt][2] + bcol0[nt]);
                o1.y = elu1(acc[mt][nt][3] + bcol1[nt]);
            }
            *(float2*)(C + (size_t)ra * HID + col)       = o0;
            *(float2*)(C + (size_t)(ra + 8) * HID + col) = o1;
        }
    }
}

// ---------------------------------------------------------------------------
__global__ void __launch_bounds__(256)
wprep_kernel(const float* __restrict__ W2, const float* __restrict__ W4,
             const float* __restrict__ Ws, float* __restrict__ out)
{
    int i = blockIdx.x * 256 + threadIdx.x;   // grid 768 -> 196608
    const float* src;
    int j = i;
    if (i < 65536)        { src = W2; }
    else if (i < 131072)  { src = W4; j = i - 65536; }
    else                  { src = Ws; j = i - 131072; }
    out[i] = __uint_as_float(f2tf(src[j]));
}

// ---------------------------------------------------------------------------
template <int BK, bool DO_ELU, bool HAS_BIAS>
__global__ void __launch_bounds__(256, 2)
gemm_kernel(const float* __restrict__ A, const float* __restrict__ Bm,
            const float* __restrict__ Bm_hi,
            const float* __restrict__ bias, float* __restrict__ C,
            int K, int ldb, int ldc)
{
    const int tid  = threadIdx.x;
    const int tx   = tid & 15;
    const int ty   = tid >> 4;
    const int row0 = blockIdx.x * 128;
    const int col0 = blockIdx.y * 128;
    int colB = col0;
    const float* B = Bm;
    if (Bm_hi != nullptr && col0 >= 256) { B = Bm_hi; colB = col0 - 256; }

    __shared__ float As[BK][132];
    __shared__ float Bs[BK][128];

    float acc[8][8];
#pragma unroll
    for (int i = 0; i < 8; i++)
#pragma unroll
        for (int j = 0; j < 8; j++) acc[i][j] = 0.f;

    const int NT = K / BK;
    for (int t = 0; t < NT; t++) {
        const int k0 = t * BK;
        if constexpr (BK == 8) {
            const int am = tid >> 1, ac = (tid & 1) * 4;
            float4 v = *(const float4*)(A + (size_t)(row0 + am) * K + k0 + ac);
            As[ac + 0][am] = v.x; As[ac + 1][am] = v.y;
            As[ac + 2][am] = v.z; As[ac + 3][am] = v.w;
            const int bk = tid >> 5, bn = (tid & 31) * 4;
            *(float4*)&Bs[bk][bn] =
                *(const float4*)(B + (size_t)(k0 + bk) * ldb + colB + bn);
        } else {
            const int am = tid >> 1, ac = (tid & 1) * 8;
            const float* ap = A + (size_t)(row0 + am) * K + k0 + ac;
            float4 v0 = *(const float4*)(ap);
            float4 v1 = *(const float4*)(ap + 4);
            As[ac + 0][am] = v0.x; As[ac + 1][am] = v0.y;
            As[ac + 2][am] = v0.z; As[ac + 3][am] = v0.w;
            As[ac + 4][am] = v1.x; As[ac + 5][am] = v1.y;
            As[ac + 6][am] = v1.z; As[ac + 7][am] = v1.w;
            const int bk = tid >> 4, bn = (tid & 15) * 8;
            const float* bp = B + (size_t)(k0 + bk) * ldb + colB + bn;
            *(float4*)&Bs[bk][bn]     = *(const float4*)(bp);
            *(float4*)&Bs[bk][bn + 4] = *(const float4*)(bp + 4);
        }
        __syncthreads();
#pragma unroll
        for (int k = 0; k < BK; k++) {
            float a[8], bb[8];
            *(float4*)&a[0]  = *(const float4*)&As[k][ty * 8];
            *(float4*)&a[4]  = *(const float4*)&As[k][ty * 8 + 4];
            *(float4*)&bb[0] = *(const float4*)&Bs[k][tx * 8];
            *(float4*)&bb[4] = *(const float4*)&Bs[k][tx * 8 + 4];
#pragma unroll
            for (int i = 0; i < 8; i++)
#pragma unroll
                for (int j = 0; j < 8; j++)
                    acc[i][j] = fmaf(a[i], bb[j], acc[i][j]);
        }
        __syncthreads();
    }

    float bv[8];
#pragma unroll
    for (int j = 0; j < 8; j++)
        bv[j] = HAS_BIAS ? bias[colB + tx * 8 + j] : 0.f;
#pragma unroll
    for (int i = 0; i < 8; i++) {
        float o[8];
#pragma unroll
        for (int j = 0; j < 8; j++) {
            float v = acc[i][j] + bv[j];
            o[j] = DO_ELU ? elu1(v) : v;
        }
        float* cp = C + (size_t)(row0 + ty * 8 + i) * ldc + col0 + tx * 8;
        *(float4*)(cp)     = *(float4*)&o[0];
        *(float4*)(cp + 4) = *(float4*)&o[4];
    }
}

// ---------------------------------------------------------------------------
__global__ void __launch_bounds__(256)
edge2node_kernel(const float* __restrict__ x2, float* __restrict__ inc)
{
    int row = blockIdx.x;
    int c   = threadIdx.x;
    int b   = row / N_NODE;
    int n   = row - b * N_NODE;
    const float* base = x2 + ((size_t)(b * N_EDGE + n * 99)) * HID + c;
    float s = 0.f;
#pragma unroll 4
    for (int t = 0; t < 99; t++) s += base[(size_t)t * HID];
    inc[(size_t)row * HID + c] = s * (1.0f / (float)N_EDGE);
}

__global__ void __launch_bounds__(256)
bn_partial_kernel(const float* __restrict__ x4,
                  float* __restrict__ psum, float* __restrict__ psq)
{
    int c = threadIdx.x, g = blockIdx.x;
    const float* base = x4 + (size_t)g * ROWS_PER_PART * HID + c;
    float s = 0.f, q = 0.f;
    for (int r = 0; r < ROWS_PER_PART; r++) {
        float v = base[(size_t)r * HID];
        s += v;
        q = fmaf(v, v, q);
    }
    psum[g * HID + c] = s;
    psq [g * HID + c] = q;
}

__global__ void __launch_bounds__(256)
bn_final_kernel(const float* __restrict__ psum, const float* __restrict__ psq,
                const float* __restrict__ gamma, const float* __restrict__ beta,
                const float* __restrict__ fcW, const float* __restrict__ fcb,
                float* __restrict__ Wp, float* __restrict__ bp)
{
    int c = threadIdx.x;
    float s = 0.f, q = 0.f;
    for (int g = 0; g < NPART; g++) {
        s += psum[g * HID + c];
        q += psq [g * HID + c];
    }
    const float invM = 1.0f / (float)ROWS_EDGE;
    float m   = s * invM;
    float var = q * invM - m * m;
    float sc  = gamma[c] * rsqrtf(var + 1e-5f);
    float sh  = beta[c] - m * sc;
    float w0  = fcW[c * 2 + 0], w1 = fcW[c * 2 + 1];
    Wp[c]       = sc * w0;
    Wp[HID + c] = sc * w1;

    __shared__ float r0[256], r1[256];
    r0[c] = sh * w0;
    r1[c] = sh * w1;
    __syncthreads();
    for (int off = 128; off > 0; off >>= 1) {
        if (c < off) { r0[c] += r0[c + off]; r1[c] += r1[c + off]; }
        __syncthreads();
    }
    if (c == 0) {
        bp[0] = r0[0] + fcb[0];
        bp[1] = r1[0] + fcb[1];
    }
}

__global__ void __launch_bounds__(256)
out_kernel(const float* __restrict__ x4, const float* __restrict__ Wp,
           const float* __restrict__ bp, float* __restrict__ out)
{
    __shared__ float w0[256], w1[256];
    __shared__ float bsh[2];
    int tid = threadIdx.x;
    w0[tid] = Wp[tid];
    w1[tid] = Wp[256 + tid];
    if (tid < 2) bsh[tid] = bp[tid];
    __syncthreads();

    int warp = tid >> 5, lane = tid & 31;
    size_t row = (size_t)blockIdx.x * 8 + warp;
    const float4* xr = (const float4*)(x4 + row * HID);
    float s0 = 0.f, s1 = 0.f;
#pragma unroll
    for (int u = 0; u < 2; u++) {
        float4 xv = xr[lane + u * 32];
        int cb = (lane + u * 32) * 4;
        float4 a = *(const float4*)&w0[cb];
        float4 b = *(const float4*)&w1[cb];
        s0 += xv.x * a.x + xv.y * a.y + xv.z * a.z + xv.w * a.w;
        s1 += xv.x * b.x + xv.y * b.y + xv.z * b.z + xv.w * b.w;
    }
#pragma unroll
    for (int off = 16; off; off >>= 1) {
        s0 += __shfl_xor_sync(0xffffffffu, s0, off);
        s1 += __shfl_xor_sync(0xffffffffu, s1, off);
    }
    if (lane == 0) {
        out[row * 2 + 0] = s0 + bsh[0];
        out[row * 2 + 1] = s1 + bsh[1];
    }
}

// ---------------------------------------------------------------------------
extern "C" void kernel_launch(void* const* d_in, const int* in_sizes, int n_in,
                              void* d_out, int out_size)
{
    (void)in_sizes; (void)n_in; (void)out_size;

    const float* x_in = (const float*)d_in[0];
    const float* W1_1 = (const float*)d_in[3];
    const float* b1_1 = (const float*)d_in[4];
    const float* W1_2 = (const float*)d_in[5];
    const float* b1_2 = (const float*)d_in[6];
    const float* W2_1 = (const float*)d_in[7];
    const float* b2_1 = (const float*)d_in[8];
    const float* W2_2 = (const float*)d_in[9];
    const float* b2_2 = (const float*)d_in[10];
    const float* W3_1 = (const float*)d_in[11];
    const float* b3_1 = (const float*)d_in[12];
    const float* W3_2 = (const float*)d_in[13];
    const float* b3_2 = (const float*)d_in[14];
    const float* W4_1 = (const float*)d_in[15];
    const float* b4_1 = (const float*)d_in[16];
    const float* W4_2 = (const float*)d_in[17];
    const float* b4_2 = (const float*)d_in[18];
    const float* bn_g = (const float*)d_in[19];
    const float* bn_b = (const float*)d_in[20];
    const float* fcW  = (const float*)d_in[21];
    const float* fcb  = (const float*)d_in[22];
    float* out = (float*)d_out;

    float* scratch = nullptr;
    cudaGetSymbolAddress((void**)&scratch, g_scratch);

    float* h1a  = scratch + OFF_H1A;
    float* h1   = scratch + OFF_H1;
    float* SR   = scratch + OFF_SR;      // [3200,512]: send | recv halves
    float* inc  = scratch + OFF_INC;
    float* h3a  = scratch + OFF_H3A;
    float* h3   = scratch + OFF_H3;
    float* AC   = scratch + OFF_AC;      // [3200,512]
    float* x2   = scratch + OFF_X2;
    float* skip = scratch + OFF_SKIP;
    float* x4   = scratch + OFF_X4;
    float* psum = scratch + OFF_PSUM;
    float* psq  = scratch + OFF_PSQ;
    float* Wp   = scratch + OFF_WP;
    float* bpv  = scratch + OFF_BP;
    float* WT2  = scratch + OFF_WT;            // tf32(W2_2)
    float* WT4  = scratch + OFF_WT + 65536;    // tf32(W4_2)
    float* WTS  = scratch + OFF_WT + 131072;   // tf32(W4_1[512:768])

    static cudaStream_t s2 = nullptr;
    static cudaEvent_t evF0 = nullptr, evW = nullptr, evF1 = nullptr, evN = nullptr;
    static bool inited = false;
    if (!inited) {
        cudaFuncSetAttribute((const void*)edge_tf32_kernel<0>,
                             cudaFuncAttributeMaxDynamicSharedMemorySize, EDGE_SMEM_BYTES);
        cudaFuncSetAttribute((const void*)edge_tf32_kernel<1>,
                             cudaFuncAttributeMaxDynamicSharedMemorySize, EDGE_SMEM_BYTES);
        cudaFuncSetAttribute((const void*)edge_tf32_kernel<2>,
                             cudaFuncAttributeMaxDynamicSharedMemorySize, EDGE_SMEM_BYTES);
        cudaStreamCreateWithFlags(&s2, cudaStreamNonBlocking);
        cudaEventCreateWithFlags(&evF0, cudaEventDisableTiming);
        cudaEventCreateWithFlags(&evW,  cudaEventDisableTiming);
        cudaEventCreateWithFlags(&evF1, cudaEventDisableTiming);
        cudaEventCreateWithFlags(&evN,  cudaEventDisableTiming);
        inited = true;
    }

    dim3 blk(256);
    dim3 gn(ROWS_NODE / 128, 2);        // (25, 2)
    dim3 gw(ROWS_NODE / 128, 4);        // (25, 4)  merged wide-N
    const int gedge = ROWS_EDGE / 128;  // 2475

    // ---- fork 0: wprep on s2 concurrent with mlp1 chain on main ----
    cudaEventRecord(evF0, 0);
    cudaStreamWaitEvent(s2, evF0, 0);
    wprep_kernel<<<768, blk, 0, s2>>>(W2_2, W4_2, W4_1 + 512 * 256,
                                      scratch + OFF_WT);
    cudaEventRecord(evW, s2);

    // main: mlp1 (exact fp32) -> SR merge
    gemm_kernel<8,  true,  true ><<<gn, blk>>>(x_in, W1_1, nullptr, b1_1, h1a,
                                               K_IN, HID, HID);
    gemm_kernel<16, true,  true ><<<gn, blk>>>(h1a, W1_2, nullptr, b1_2, h1,
                                               HID, HID, HID);
    gemm_kernel<16, false, false><<<gw, blk>>>(h1, W2_1, W2_1 + 65536, nullptr, SR,
                                               HID, HID, 512);
    // join: edge GEMM 1 needs WT2 (s2) + SR (main)
    cudaStreamWaitEvent(0, evW, 0);
    edge_tf32_kernel<1><<<gedge, blk, EDGE_SMEM_BYTES>>>(
        SR, SR + 256, nullptr, b2_1, WT2, b2_2, x2, 512);

    // ---- fork 1: node chain on s2 concurrent with skip GEMM on main ----
    cudaEventRecord(evF1, 0);
    cudaStreamWaitEvent(s2, evF1, 0);
    edge2node_kernel<<<ROWS_NODE, blk, 0, s2>>>(x2, inc);
    gemm_kernel<16, true,  true ><<<gn, blk, 0, s2>>>(inc, W3_1, nullptr, b3_1, h3a,
                                                      HID, HID, HID);
    gemm_kernel<16, true,  true ><<<gn, blk, 0, s2>>>(h3a, W3_2, nullptr, b3_2, h3,
                                                      HID, HID, HID);
    gemm_kernel<16, false, false><<<gw, blk, 0, s2>>>(h3, W4_1, W4_1 + 65536,
                                                      nullptr, AC, HID, HID, 512);
    cudaEventRecord(evN, s2);

    // main: skip GEMM (x2 @ W4_1[512:768])
    edge_tf32_kernel<0><<<gedge, blk, EDGE_SMEM_BYTES>>>(
        x2, nullptr, nullptr, nullptr, WTS, nullptr, skip, 0);

    // join: edge GEMM 3 needs skip (main) + AC (s2)
    cudaStreamWaitEvent(0, evN, 0);
    edge_tf32_kernel<2><<<gedge, blk, EDGE_SMEM_BYTES>>>(
        AC, AC + 256, skip, b4_1, WT4, b4_2, x4, 512);

    // batchnorm stats (deterministic two-pass) + fc fold + final GEMV
    bn_partial_kernel<<<NPART, blk>>>(x4, psum, psq);
    bn_final_kernel<<<1, blk>>>(psum, psq, bn_g, bn_b, fcW, fcb, Wp, bpv);
    out_kernel<<<ROWS_EDGE / 8, blk>>>(x4, Wp, bpv, out);
}